// round 16
// baseline (speedup 1.0000x reference)
#include <cuda_runtime.h>
#include <math.h>
#include <stdint.h>

// ---------------------------------------------------------------------------
// Problem constants
// ---------------------------------------------------------------------------
#define BATCH 64
#define GRID_N 32
#define TOK 1024
#define HID 1024

// GEMM tiling: CTA 128x128x32, 4 warps of 64x64, 2-stage cp.async pipeline
#define BK 32
#define A_STRIDE 36        // words per A smem row (conflict-free: 4g+c)
#define B_STRIDE 136       // words per B smem row (conflict-free: 8c+g)
#define A_BYTES (128 * A_STRIDE * 4)    // 18432
#define B_BYTES (BK * B_STRIDE * 4)     // 17408
#define STAGE_BYTES (A_BYTES + B_BYTES) // 35840
#define SMEM_DYN (2 * STAGE_BYTES)      // 71680

// ---------------------------------------------------------------------------
// Scratch (device globals -- no allocation allowed)
// ---------------------------------------------------------------------------
__device__ float g_x336[BATCH * 3 * 336 * 336];
__device__ float g_patches[BATCH * 1024 * 608];   // Kp=608 E0/E1; E2 (196x3072) fits
__device__ float g_feat[BATCH * 1024 * 1024];     // tower out (E2: 12544x1152 fits)
__device__ float g_feat2[BATCH * 1024 * 1152];
__device__ float g_wi[3 * BATCH];
__device__ float g_wbuf[7643136];                 // tf32-rounded, K-padded weights

// weight offsets inside g_wbuf (all K padded to mult of 32)
#define OFF_WT0 0               // 608 x 1024
#define OFF_WT1 622592          // 608 x 768
#define OFF_WT2 1089536         // 3072 x 1152
#define OFF_WP0 4628480         // 1024 x 1024
#define OFF_WP1 5677056         // 768 x 1024
#define OFF_WP2 6463488         // 1152 x 1024

// ---------------------------------------------------------------------------
// Helpers
// ---------------------------------------------------------------------------
__device__ __forceinline__ uint32_t smem_u32(const void* p) {
    uint32_t a;
    asm("{ .reg .u64 t; cvta.to.shared.u64 t, %1; cvt.u32.u64 %0, t; }"
        : "=r"(a) : "l"(p));
    return a;
}
__device__ __forceinline__ float tf32r(float x) {
    uint32_t r;
    asm("cvt.rna.tf32.f32 %0, %1;" : "=r"(r) : "f"(x));
    return __uint_as_float(r);
}
__device__ __forceinline__ void cp16(uint32_t dst, const float* src) {
    asm volatile("cp.async.cg.shared.global [%0], [%1], 16;" :: "r"(dst), "l"(src));
}
#define CP_COMMIT() asm volatile("cp.async.commit_group;" ::: "memory")
#define CP_WAIT1()  asm volatile("cp.async.wait_group 1;" ::: "memory")
#define CP_WAIT0()  asm volatile("cp.async.wait_group 0;" ::: "memory")

__device__ __forceinline__ void mma_tf32(float* d, const uint32_t* a, const uint32_t* b) {
    asm volatile(
        "mma.sync.aligned.m16n8k8.row.col.f32.tf32.tf32.f32 "
        "{%0,%1,%2,%3}, {%4,%5,%6,%7}, {%8,%9}, {%0,%1,%2,%3};\n"
        : "+f"(d[0]), "+f"(d[1]), "+f"(d[2]), "+f"(d[3])
        : "r"(a[0]), "r"(a[1]), "r"(a[2]), "r"(a[3]),
          "r"(b[0]), "r"(b[1]));
}

// ---------------------------------------------------------------------------
// Prep: round weights to tf32-exact fp32, zero-pad K to Kdst rows
// ---------------------------------------------------------------------------
__global__ void prep_kernel(const float* __restrict__ src, float* __restrict__ dst,
                            int Ksrc, int Kdst, int N) {
    int idx = blockIdx.x * blockDim.x + threadIdx.x;
    if (idx >= Kdst * N) return;
    int k = idx / N;
    dst[idx] = (k < Ksrc) ? tf32r(src[(size_t)k * N + (idx % N)]) : 0.f;
}

// ---------------------------------------------------------------------------
// Routing weights
// ---------------------------------------------------------------------------
__global__ void wi_kernel(const int* __restrict__ sel, const float* __restrict__ rw) {
    int b = threadIdx.x;
    if (b >= BATCH) return;
    float w0 = 0.f, w1 = 0.f, w2 = 0.f;
    #pragma unroll
    for (int k = 0; k < 2; k++) {
        int e = sel[b * 2 + k];
        float r = rw[b * 2 + k];
        if (e == 0) w0 += r; else if (e == 1) w1 += r; else w2 += r;
    }
    g_wi[0 * BATCH + b] = w0;
    g_wi[1 * BATCH + b] = w1;
    g_wi[2 * BATCH + b] = w2;
}

// ---------------------------------------------------------------------------
// Bilinear image resize 448 -> 336, align_corners=True
// ---------------------------------------------------------------------------
__global__ void resize_img_kernel(const float* __restrict__ x) {
    const int S = 336, H = 448;
    int idx = blockIdx.x * blockDim.x + threadIdx.x;
    if (idx >= BATCH * 3 * S * S) return;
    int ox = idx % S;
    int oy = (idx / S) % S;
    int bc = idx / (S * S);
    float fy = (float)oy * ((float)(H - 1) / (float)(S - 1));
    float fx = (float)ox * ((float)(H - 1) / (float)(S - 1));
    int y0 = (int)floorf(fy); y0 = min(max(y0, 0), H - 1);
    int x0 = (int)floorf(fx); x0 = min(max(x0, 0), H - 1);
    int y1 = min(y0 + 1, H - 1);
    int x1 = min(x0 + 1, H - 1);
    float ty = fy - (float)y0, tx = fx - (float)x0;
    const float* p = x + (size_t)bc * H * H;
    float a = p[y0 * H + x0] * (1.f - ty) + p[y1 * H + x0] * ty;
    float b = p[y0 * H + x1] * (1.f - ty) + p[y1 * H + x1] * ty;
    g_x336[idx] = a * (1.f - tx) + b * tx;
}

// ---------------------------------------------------------------------------
// Patchify (tf32-rounded, zero-padded to Kp)
// ---------------------------------------------------------------------------
__global__ void patchify_kernel(const float* __restrict__ src,
                                int s, int p, int g, int K, int Kp) {
    int idx = blockIdx.x * blockDim.x + threadIdx.x;
    if (idx >= BATCH * g * g * Kp) return;
    int kk = idx % Kp;
    int t  = (idx / Kp) % (g * g);
    int b  = idx / (Kp * g * g);
    float v = 0.f;
    if (kk < K) {
        int pp = p * p;
        int ch = kk / pp;
        int r  = kk % pp;
        int py = r / p, px = r % p;
        int gy = t / g, gx = t % g;
        v = tf32r(src[(((size_t)b * 3 + ch) * s + (gy * p + py)) * s + (gx * p + px)]);
    }
    g_patches[idx] = v;
}

// ---------------------------------------------------------------------------
// Feature grid bilinear resize g x g -> 32 x 32 (tf32-rounded output)
// ---------------------------------------------------------------------------
__global__ void resize_feat_kernel(int g, int c, int in_stride) {
    int idx = blockIdx.x * blockDim.x + threadIdx.x;
    if (idx >= BATCH * TOK * c) return;
    int ch = idx % c;
    int t  = (idx / c) % TOK;
    int b  = idx / (c * TOK);
    int ty = t / GRID_N, tx = t % GRID_N;
    float fy = (float)ty * ((float)(g - 1) / (float)(GRID_N - 1));
    float fx = (float)tx * ((float)(g - 1) / (float)(GRID_N - 1));
    int y0 = (int)floorf(fy); y0 = min(max(y0, 0), g - 1);
    int x0 = (int)floorf(fx); x0 = min(max(x0, 0), g - 1);
    int y1 = min(y0 + 1, g - 1);
    int x1 = min(x0 + 1, g - 1);
    float dy = fy - (float)y0, dx = fx - (float)x0;
    const float* fb = g_feat + (size_t)b * g * g * in_stride + ch;
    float v00 = fb[(size_t)(y0 * g + x0) * in_stride];
    float v01 = fb[(size_t)(y0 * g + x1) * in_stride];
    float v10 = fb[(size_t)(y1 * g + x0) * in_stride];
    float v11 = fb[(size_t)(y1 * g + x1) * in_stride];
    g_feat2[idx] = tf32r((v00 * (1.f - dy) + v10 * dy) * (1.f - dx)
                       + (v01 * (1.f - dy) + v11 * dy) * dx);
}

// ---------------------------------------------------------------------------
// TF32 HMMA GEMM: C[M,N] = A[M,Kp] @ B[Kp,N] + bias (+scale, +acc, +round)
//   CTA 128x128, 128 threads, 4 warps of 64x64 (4x8 frags m16n8k8).
//   2-stage cp.async pipeline; inputs pre-rounded to tf32-exact, K pre-padded
//   to KT*32 (A row stride lda >= KT*32, zero tail; B has KT*32 rows).
//   M%128==0, N%128==0, lda%32==0, ldb%4==0, 16B-aligned bases.
// ---------------------------------------------------------------------------
__global__ __launch_bounds__(128, 2)
void tf32_gemm(const float* __restrict__ A, int lda,
               const float* __restrict__ B, int ldb, int KT,
               const float* __restrict__ bias,
               float* __restrict__ C, int ldc,
               const float* __restrict__ rowscale,
               int accumulate, int round_out) {
    extern __shared__ char sb[];
    const uint32_t s0 = smem_u32(sb);

    const int tid  = threadIdx.x;
    const int lane = tid & 31;
    const int warp = tid >> 5;
    const int wm   = warp & 1;     // row half
    const int wn   = warp >> 1;    // col half
    const int g    = lane >> 2;    // 0..7
    const int c    = lane & 3;     // 0..3

    const int row0 = blockIdx.y * 128;
    const int col0 = blockIdx.x * 128;

    // cp.async source pointers / smem dest offsets
    // A: thread covers (m = tid>>3 + 16*i, kq = tid&7), 8 iters
    const float* Ag = A + (size_t)(row0 + (tid >> 3)) * lda + (tid & 7) * 4;
    const uint32_t Ad0 = s0 + (tid >> 3) * (A_STRIDE * 4) + (tid & 7) * 16;
    // B: thread covers (k = tid>>5 + 4*i, nq = tid&31), 8 iters
    const float* Bg = B + (size_t)(tid >> 5) * ldb + col0 + (tid & 31) * 4;
    const uint32_t Bd0 = s0 + A_BYTES + (tid >> 5) * (B_STRIDE * 4) + (tid & 31) * 16;

    float acc[4][8][4];
    #pragma unroll
    for (int mi = 0; mi < 4; mi++)
        #pragma unroll
        for (int ni = 0; ni < 8; ni++)
            #pragma unroll
            for (int r = 0; r < 4; r++) acc[mi][ni][r] = 0.f;

    // ---- prologue: stage 0 ----
    {
        #pragma unroll
        for (int i = 0; i < 8; i++)
            cp16(Ad0 + i * 16 * (A_STRIDE * 4), Ag + (size_t)(16 * i) * lda);
        #pragma unroll
        for (int i = 0; i < 8; i++)
            cp16(Bd0 + i * 4 * (B_STRIDE * 4), Bg + (size_t)(4 * i) * ldb);
        CP_COMMIT();
    }

    for (int t = 0; t < KT; t++) {
        const int buf = t & 1;
        if (t + 1 < KT) {
            const int nb = (t + 1) & 1;
            const int k0 = (t + 1) * BK;
            const uint32_t ad = Ad0 + nb * STAGE_BYTES;
            const uint32_t bd = Bd0 + nb * STAGE_BYTES;
            const float* ag = Ag + k0;
            const float* bg = Bg + (size_t)k0 * ldb;
            #pragma unroll
            for (int i = 0; i < 8; i++)
                cp16(ad + i * 16 * (A_STRIDE * 4), ag + (size_t)(16 * i) * lda);
            #pragma unroll
            for (int i = 0; i < 8; i++)
                cp16(bd + i * 4 * (B_STRIDE * 4), bg + (size_t)(4 * i) * ldb);
            CP_COMMIT();
            CP_WAIT1();
        } else {
            CP_WAIT0();
        }
        __syncthreads();

        const uint32_t* As  = (const uint32_t*)(sb + buf * STAGE_BYTES);
        const uint32_t* Bs  = (const uint32_t*)(sb + buf * STAGE_BYTES + A_BYTES);

        #pragma unroll
        for (int ks = 0; ks < BK; ks += 8) {
            uint32_t af[4][4];
            uint32_t bf[8][2];
            #pragma unroll
            for (int mi = 0; mi < 4; mi++) {
                int row = wm * 64 + mi * 16 + g;
                const uint32_t* a0 = As + row * A_STRIDE + ks + c;
                af[mi][0] = a0[0];
                af[mi][1] = a0[8 * A_STRIDE];
                af[mi][2] = a0[4];
                af[mi][3] = a0[8 * A_STRIDE + 4];
            }
            #pragma unroll
            for (int ni = 0; ni < 8; ni++) {
                int col = wn * 64 + ni * 8 + g;
                const uint32_t* b0 = Bs + (ks + c) * B_STRIDE + col;
                bf[ni][0] = b0[0];
                bf[ni][1] = b0[4 * B_STRIDE];
            }
            #pragma unroll
            for (int mi = 0; mi < 4; mi++)
                #pragma unroll
                for (int ni = 0; ni < 8; ni++)
                    mma_tf32(acc[mi][ni], af[mi], bf[ni]);
        }
        __syncthreads();
    }

    // ---- epilogue ----
    float scale = 1.f;
    if (rowscale) scale = rowscale[row0 >> 10];

    #pragma unroll
    for (int mi = 0; mi < 4; mi++) {
        int r0 = row0 + wm * 64 + mi * 16 + g;
        #pragma unroll
        for (int ni = 0; ni < 8; ni++) {
            int col = col0 + wn * 64 + ni * 8 + 2 * c;
            float b0 = __ldg(bias + col), b1 = __ldg(bias + col + 1);

            float2 v0, v1;
            v0.x = (acc[mi][ni][0] + b0) * scale;
            v0.y = (acc[mi][ni][1] + b1) * scale;
            v1.x = (acc[mi][ni][2] + b0) * scale;
            v1.y = (acc[mi][ni][3] + b1) * scale;

            float* p0 = C + (size_t)r0 * ldc + col;
            float* p1 = C + (size_t)(r0 + 8) * ldc + col;
            if (accumulate) {
                float2 o0 = *(float2*)p0;
                float2 o1 = *(float2*)p1;
                v0.x += o0.x; v0.y += o0.y;
                v1.x += o1.x; v1.y += o1.y;
            }
            if (round_out) {
                v0.x = tf32r(v0.x); v0.y = tf32r(v0.y);
                v1.x = tf32r(v1.x); v1.y = tf32r(v1.y);
            }
            *(float2*)p0 = v0;
            *(float2*)p1 = v1;
        }
    }
}

// ---------------------------------------------------------------------------
// Launch
// ---------------------------------------------------------------------------
extern "C" void kernel_launch(void* const* d_in, const int* in_sizes, int n_in,
                              void* d_out, int out_size) {
    const float* x   = (const float*)d_in[0];
    const int*   sel = (const int*)d_in[1];
    const float* rw  = (const float*)d_in[2];
    const float* wt[3] = {(const float*)d_in[3],  (const float*)d_in[7],  (const float*)d_in[11]};
    const float* bt[3] = {(const float*)d_in[4],  (const float*)d_in[8],  (const float*)d_in[12]};
    const float* wp[3] = {(const float*)d_in[5],  (const float*)d_in[9],  (const float*)d_in[13]};
    const float* bp[3] = {(const float*)d_in[6],  (const float*)d_in[10], (const float*)d_in[14]};
    float* out = (float*)d_out;

    float *p_x336, *p_patches, *p_feat, *p_feat2, *p_wi, *p_wbuf;
    cudaGetSymbolAddress((void**)&p_x336,    g_x336);
    cudaGetSymbolAddress((void**)&p_patches, g_patches);
    cudaGetSymbolAddress((void**)&p_feat,    g_feat);
    cudaGetSymbolAddress((void**)&p_feat2,   g_feat2);
    cudaGetSymbolAddress((void**)&p_wi,      g_wi);
    cudaGetSymbolAddress((void**)&p_wbuf,    g_wbuf);

    cudaFuncSetAttribute(tf32_gemm, cudaFuncAttributeMaxDynamicSharedMemorySize, SMEM_DYN);

    const int T = 256;
    wi_kernel<<<1, 64>>>(sel, rw);

    // Weight prep (round to tf32-exact, K-pad to mult of 32)
    auto prep = [&](const float* s, float* d, int Ks, int Kd, int N) {
        prep_kernel<<<(Kd * N + T - 1) / T, T>>>(s, d, Ks, Kd, N);
    };
    prep(wt[0], p_wbuf + OFF_WT0, 588, 608, 1024);
    prep(wt[1], p_wbuf + OFF_WT1, 588, 608, 768);
    prep(wt[2], p_wbuf + OFF_WT2, 3072, 3072, 1152);
    prep(wp[0], p_wbuf + OFF_WP0, 1024, 1024, 1024);
    prep(wp[1], p_wbuf + OFF_WP1, 768, 768, 1024);
    prep(wp[2], p_wbuf + OFF_WP2, 1152, 1152, 1024);

    // ---------------- Expert 0: s=448, p=14, g=32, c=1024 ------------------
    {
        int g = 32, Kp = 608, c = 1024;
        patchify_kernel<<<(BATCH * g * g * Kp + T - 1) / T, T>>>(x, 448, 14, g, 588, Kp);
        // tower: [65536 x 588] @ [588 x 1024] -> g_feat (rounded; feeds proj)
        tf32_gemm<<<dim3(c / 128, BATCH * g * g / 128), 128, SMEM_DYN>>>(
            p_patches, Kp, p_wbuf + OFF_WT0, c, Kp / 32, bt[0],
            p_feat, c, nullptr, 0, 1);
        // proj: [65536 x 1024] @ [1024 x 1024] -> out (scaled)
        tf32_gemm<<<dim3(HID / 128, BATCH * TOK / 128), 128, SMEM_DYN>>>(
            p_feat, c, p_wbuf + OFF_WP0, HID, c / 32, bp[0],
            out, HID, p_wi + 0 * BATCH, 0, 0);
    }

    // ---------------- Expert 1: s=336, p=14, g=24, c=768 -------------------
    {
        int g = 24, Kp = 608, c = 768;
        resize_img_kernel<<<(BATCH * 3 * 336 * 336 + T - 1) / T, T>>>(x);
        patchify_kernel<<<(BATCH * g * g * Kp + T - 1) / T, T>>>(p_x336, 336, 14, g, 588, Kp);
        tf32_gemm<<<dim3(c / 128, BATCH * g * g / 128), 128, SMEM_DYN>>>(
            p_patches, Kp, p_wbuf + OFF_WT1, c, Kp / 32, bt[1],
            p_feat, c, nullptr, 0, 0);
        resize_feat_kernel<<<(BATCH * TOK * c + T - 1) / T, T>>>(g, c, c);
        tf32_gemm<<<dim3(HID / 128, BATCH * TOK / 128), 128, SMEM_DYN>>>(
            p_feat2, c, p_wbuf + OFF_WP1, HID, c / 32, bp[1],
            out, HID, p_wi + 1 * BATCH, 1, 0);
    }

    // ---------------- Expert 2: s=448, p=32, g=14, c=1152 ------------------
    {
        int g = 14, K = 3072, c = 1152;
        patchify_kernel<<<(BATCH * g * g * K + T - 1) / T, T>>>(x, 448, 32, g, K, K);
        // tower: [12544 x 3072] @ [3072 x 1152] -> g_feat (ldc=1152)
        tf32_gemm<<<dim3(c / 128, BATCH * g * g / 128), 128, SMEM_DYN>>>(
            p_patches, K, p_wbuf + OFF_WT2, c, K / 32, bt[2],
            p_feat, c, nullptr, 0, 0);
        resize_feat_kernel<<<(BATCH * TOK * c + T - 1) / T, T>>>(g, c, c);
        tf32_gemm<<<dim3(HID / 128, BATCH * TOK / 128), 128, SMEM_DYN>>>(
            p_feat2, c, p_wbuf + OFF_WP2, HID, c / 32, bp[2],
            out, HID, p_wi + 2 * BATCH, 1, 0);
    }
}

// round 17
// speedup vs baseline: 1.2920x; 1.2920x over previous
#include <cuda_runtime.h>
#include <math.h>
#include <stdint.h>

// ---------------------------------------------------------------------------
// Problem constants
// ---------------------------------------------------------------------------
#define BATCH 64
#define GRID_N 32
#define TOK 1024
#define HID 1024

// GEMM tiling: CTA 128x256x32, 256 threads, 8 warps (2x4) of 64x64, 3 stages
#define BK 32
#define A_ST 36            // words per A smem row  (bank = 4g+c, conflict-free)
#define B_ST 264           // words per B smem row  (bank = 8c+g, conflict-free)
#define A_BYTES (128 * A_ST * 4)        // 18432
#define B_BYTES (BK * B_ST * 4)         // 33792
#define STAGE_BYTES (A_BYTES + B_BYTES) // 52224
#define STAGES 3
#define SMEM_DYN (STAGES * STAGE_BYTES) // 156672

// ---------------------------------------------------------------------------
// Scratch (device globals -- no allocation allowed)
// ---------------------------------------------------------------------------
__device__ float g_x336[BATCH * 3 * 336 * 336];
__device__ float g_patches[BATCH * 1024 * 608];   // E0/E1 Kp=608; E2 196x3072 fits
__device__ float g_feat[BATCH * 1024 * 1024];     // tower out (E2: 12544x1280 fits)
__device__ float g_feat2[BATCH * 1024 * 1152];
__device__ float g_wi[3 * BATCH];
__device__ float g_wbuf[8036352];                 // tf32-rounded, K/N-padded weights
__device__ float g_btp[1280];                     // padded E2 tower bias

// weight offsets inside g_wbuf
#define OFF_WT0 0               // 608 x 1024
#define OFF_WT1 622592          // 608 x 768
#define OFF_WT2 1089536         // 3072 x 1280 (N padded)
#define OFF_WP0 5021696         // 1024 x 1024
#define OFF_WP1 6070272         // 768 x 1024
#define OFF_WP2 6856704         // 1152 x 1024

// ---------------------------------------------------------------------------
// Helpers
// ---------------------------------------------------------------------------
__device__ __forceinline__ uint32_t smem_u32(const void* p) {
    uint32_t a;
    asm("{ .reg .u64 t; cvta.to.shared.u64 t, %1; cvt.u32.u64 %0, t; }"
        : "=r"(a) : "l"(p));
    return a;
}
__device__ __forceinline__ float tf32r(float x) {
    uint32_t r;
    asm("cvt.rna.tf32.f32 %0, %1;" : "=r"(r) : "f"(x));
    return __uint_as_float(r);
}
__device__ __forceinline__ void cp16(uint32_t dst, const float* src) {
    asm volatile("cp.async.cg.shared.global [%0], [%1], 16;" :: "r"(dst), "l"(src));
}
#define CP_COMMIT() asm volatile("cp.async.commit_group;" ::: "memory")
#define CP_WAIT2()  asm volatile("cp.async.wait_group 2;" ::: "memory")

__device__ __forceinline__ void mma_tf32(float* d, const uint32_t* a, const uint32_t* b) {
    asm volatile(
        "mma.sync.aligned.m16n8k8.row.col.f32.tf32.tf32.f32 "
        "{%0,%1,%2,%3}, {%4,%5,%6,%7}, {%8,%9}, {%0,%1,%2,%3};\n"
        : "+f"(d[0]), "+f"(d[1]), "+f"(d[2]), "+f"(d[3])
        : "r"(a[0]), "r"(a[1]), "r"(a[2]), "r"(a[3]),
          "r"(b[0]), "r"(b[1]));
}

// ---------------------------------------------------------------------------
// Prep: round to tf32-exact (optional), pad K rows and N cols with zeros
// ---------------------------------------------------------------------------
__global__ void prep_kernel(const float* __restrict__ src, float* __restrict__ dst,
                            int Ksrc, int Kdst, int Nsrc, int Ndst, int do_round) {
    int idx = blockIdx.x * blockDim.x + threadIdx.x;
    if (idx >= Kdst * Ndst) return;
    int k = idx / Ndst, n = idx % Ndst;
    float v = 0.f;
    if (k < Ksrc && n < Nsrc) {
        v = src[(size_t)k * Nsrc + n];
        if (do_round) v = tf32r(v);
    }
    dst[idx] = v;
}

// ---------------------------------------------------------------------------
// Routing weights
// ---------------------------------------------------------------------------
__global__ void wi_kernel(const int* __restrict__ sel, const float* __restrict__ rw) {
    int b = threadIdx.x;
    if (b >= BATCH) return;
    float w0 = 0.f, w1 = 0.f, w2 = 0.f;
    #pragma unroll
    for (int k = 0; k < 2; k++) {
        int e = sel[b * 2 + k];
        float r = rw[b * 2 + k];
        if (e == 0) w0 += r; else if (e == 1) w1 += r; else w2 += r;
    }
    g_wi[0 * BATCH + b] = w0;
    g_wi[1 * BATCH + b] = w1;
    g_wi[2 * BATCH + b] = w2;
}

// ---------------------------------------------------------------------------
// Bilinear image resize 448 -> 336, align_corners=True
// ---------------------------------------------------------------------------
__global__ void resize_img_kernel(const float* __restrict__ x) {
    const int S = 336, H = 448;
    int idx = blockIdx.x * blockDim.x + threadIdx.x;
    if (idx >= BATCH * 3 * S * S) return;
    int ox = idx % S;
    int oy = (idx / S) % S;
    int bc = idx / (S * S);
    float fy = (float)oy * ((float)(H - 1) / (float)(S - 1));
    float fx = (float)ox * ((float)(H - 1) / (float)(S - 1));
    int y0 = (int)floorf(fy); y0 = min(max(y0, 0), H - 1);
    int x0 = (int)floorf(fx); x0 = min(max(x0, 0), H - 1);
    int y1 = min(y0 + 1, H - 1);
    int x1 = min(x0 + 1, H - 1);
    float ty = fy - (float)y0, tx = fx - (float)x0;
    const float* p = x + (size_t)bc * H * H;
    float a = p[y0 * H + x0] * (1.f - ty) + p[y1 * H + x0] * ty;
    float b = p[y0 * H + x1] * (1.f - ty) + p[y1 * H + x1] * ty;
    g_x336[idx] = a * (1.f - tx) + b * tx;
}

// ---------------------------------------------------------------------------
// Patchify (tf32-rounded, zero-padded to Kp)
// ---------------------------------------------------------------------------
__global__ void patchify_kernel(const float* __restrict__ src,
                                int s, int p, int g, int K, int Kp) {
    int idx = blockIdx.x * blockDim.x + threadIdx.x;
    if (idx >= BATCH * g * g * Kp) return;
    int kk = idx % Kp;
    int t  = (idx / Kp) % (g * g);
    int b  = idx / (Kp * g * g);
    float v = 0.f;
    if (kk < K) {
        int pp = p * p;
        int ch = kk / pp;
        int r  = kk % pp;
        int py = r / p, px = r % p;
        int gy = t / g, gx = t % g;
        v = tf32r(src[(((size_t)b * 3 + ch) * s + (gy * p + py)) * s + (gx * p + px)]);
    }
    g_patches[idx] = v;
}

// ---------------------------------------------------------------------------
// Feature grid bilinear resize g x g -> 32 x 32 (tf32-rounded output)
// ---------------------------------------------------------------------------
__global__ void resize_feat_kernel(int g, int c, int in_stride) {
    int idx = blockIdx.x * blockDim.x + threadIdx.x;
    if (idx >= BATCH * TOK * c) return;
    int ch = idx % c;
    int t  = (idx / c) % TOK;
    int b  = idx / (c * TOK);
    int ty = t / GRID_N, tx = t % GRID_N;
    float fy = (float)ty * ((float)(g - 1) / (float)(GRID_N - 1));
    float fx = (float)tx * ((float)(g - 1) / (float)(GRID_N - 1));
    int y0 = (int)floorf(fy); y0 = min(max(y0, 0), g - 1);
    int x0 = (int)floorf(fx); x0 = min(max(x0, 0), g - 1);
    int y1 = min(y0 + 1, g - 1);
    int x1 = min(x0 + 1, g - 1);
    float dy = fy - (float)y0, dx = fx - (float)x0;
    const float* fb = g_feat + (size_t)b * g * g * in_stride + ch;
    float v00 = fb[(size_t)(y0 * g + x0) * in_stride];
    float v01 = fb[(size_t)(y0 * g + x1) * in_stride];
    float v10 = fb[(size_t)(y1 * g + x0) * in_stride];
    float v11 = fb[(size_t)(y1 * g + x1) * in_stride];
    g_feat2[idx] = tf32r((v00 * (1.f - dy) + v10 * dy) * (1.f - dx)
                       + (v01 * (1.f - dy) + v11 * dy) * dx);
}

// ---------------------------------------------------------------------------
// TF32 HMMA GEMM: C[M,N] = A[M,Kp] @ B[Kp,N] + bias (+scale, +acc, +round)
//   CTA 128x256, 256 threads, 8 warps (2x4) of 64x64 (4x8 m16n8k8 frags).
//   3-stage cp.async pipeline; inputs pre-rounded tf32-exact, K padded to
//   KT*32 (lda >= KT*32 with zero tail rows in A; B has KT*32 rows).
//   M%128==0, N%256==0, lda%32==0, ldb%4==0, 16B-aligned bases.
// ---------------------------------------------------------------------------
__global__ __launch_bounds__(256, 1)
void tf32_gemm(const float* __restrict__ A, int lda,
               const float* __restrict__ B, int ldb, int KT,
               const float* __restrict__ bias,
               float* __restrict__ C, int ldc,
               const float* __restrict__ rowscale,
               int accumulate, int round_out) {
    extern __shared__ char sb[];
    const uint32_t s0 = smem_u32(sb);

    const int tid  = threadIdx.x;
    const int lane = tid & 31;
    const int warp = tid >> 5;
    const int wm   = warp & 1;     // 2 row slabs of 64
    const int wn   = warp >> 1;    // 4 col slabs of 64
    const int g    = lane >> 2;    // 0..7
    const int c    = lane & 3;     // 0..3

    const int row0 = blockIdx.y * 128;
    const int col0 = blockIdx.x * 256;

    // A loader: row = tid>>1 (0..127), chunk base = tid&1, 4 chunks of 16B
    const int a_row = tid >> 1;
    const int a_cb  = tid & 1;
    const float* Ag = A + (size_t)(row0 + a_row) * lda + a_cb * 4;
    const uint32_t Ad = s0 + a_row * (A_ST * 4) + a_cb * 16;
    // B loader: krow = tid>>3 (0..31), nbase = tid&7, 8 chunks of 16B
    const int b_kr = tid >> 3;
    const int b_nb = tid & 7;
    const float* Bg = B + (size_t)b_kr * ldb + col0 + b_nb * 4;
    const uint32_t Bd = s0 + A_BYTES + b_kr * (B_ST * 4) + b_nb * 16;

    float acc[4][8][4];
    #pragma unroll
    for (int mi = 0; mi < 4; mi++)
        #pragma unroll
        for (int ni = 0; ni < 8; ni++)
            #pragma unroll
            for (int r = 0; r < 4; r++) acc[mi][ni][r] = 0.f;

    // stage load: k0 = t*BK into buffer s
    auto load_stage = [&](int t, int s) {
        const int k0 = t * BK;
        const uint32_t ad = Ad + s * STAGE_BYTES;
        const uint32_t bd = Bd + s * STAGE_BYTES;
        const float* ag = Ag + k0;
        const float* bg = Bg + (size_t)k0 * ldb;
        #pragma unroll
        for (int i = 0; i < 4; i++)                    // k chunks 2i+a_cb
            cp16(ad + i * 32, ag + i * 8);
        #pragma unroll
        for (int i = 0; i < 8; i++)                    // n chunks 8i+b_nb
            cp16(bd + i * 128, bg + i * 32);
    };

    // prologue: stages 0,1
    load_stage(0, 0); CP_COMMIT();
    if (KT > 1) load_stage(1, 1);
    CP_COMMIT();

    for (int t = 0; t < KT; t++) {
        const int buf = t % STAGES;
        // issue loads for t+2 into (t+2)%3  (safe: sync at end of t-1 done)
        if (t + 2 < KT) load_stage(t + 2, (t + 2) % STAGES);
        CP_COMMIT();
        CP_WAIT2();            // <=2 pending -> stage t resident
        __syncthreads();

        const uint32_t* As = (const uint32_t*)(sb + buf * STAGE_BYTES);
        const uint32_t* Bs = (const uint32_t*)(sb + buf * STAGE_BYTES + A_BYTES);

        #pragma unroll
        for (int ks = 0; ks < BK; ks += 8) {
            uint32_t af[4][4];
            uint32_t bf[8][2];
            #pragma unroll
            for (int mi = 0; mi < 4; mi++) {
                int row = wm * 64 + mi * 16 + g;
                const uint32_t* a0 = As + row * A_ST + ks + c;
                af[mi][0] = a0[0];
                af[mi][1] = a0[8 * A_ST];
                af[mi][2] = a0[4];
                af[mi][3] = a0[8 * A_ST + 4];
            }
            #pragma unroll
            for (int ni = 0; ni < 8; ni++) {
                int col = wn * 64 + ni * 8 + g;
                const uint32_t* b0 = Bs + (ks + c) * B_ST + col;
                bf[ni][0] = b0[0];
                bf[ni][1] = b0[4 * B_ST];
            }
            #pragma unroll
            for (int mi = 0; mi < 4; mi++)
                #pragma unroll
                for (int ni = 0; ni < 8; ni++)
                    mma_tf32(acc[mi][ni], af[mi], bf[ni]);
        }
        __syncthreads();
    }

    // ---- epilogue ----
    float scale = 1.f;
    if (rowscale) scale = rowscale[row0 >> 10];

    #pragma unroll
    for (int mi = 0; mi < 4; mi++) {
        int r0 = row0 + wm * 64 + mi * 16 + g;
        #pragma unroll
        for (int ni = 0; ni < 8; ni++) {
            int col = col0 + wn * 64 + ni * 8 + 2 * c;
            float b0 = __ldg(bias + col), b1 = __ldg(bias + col + 1);

            float2 v0, v1;
            v0.x = (acc[mi][ni][0] + b0) * scale;
            v0.y = (acc[mi][ni][1] + b1) * scale;
            v1.x = (acc[mi][ni][2] + b0) * scale;
            v1.y = (acc[mi][ni][3] + b1) * scale;

            float* p0 = C + (size_t)r0 * ldc + col;
            float* p1 = C + (size_t)(r0 + 8) * ldc + col;
            if (accumulate) {
                float2 o0 = *(float2*)p0;
                float2 o1 = *(float2*)p1;
                v0.x += o0.x; v0.y += o0.y;
                v1.x += o1.x; v1.y += o1.y;
            }
            if (round_out) {
                v0.x = tf32r(v0.x); v0.y = tf32r(v0.y);
                v1.x = tf32r(v1.x); v1.y = tf32r(v1.y);
            }
            *(float2*)p0 = v0;
            *(float2*)p1 = v1;
        }
    }
}

// ---------------------------------------------------------------------------
// Launch
// ---------------------------------------------------------------------------
extern "C" void kernel_launch(void* const* d_in, const int* in_sizes, int n_in,
                              void* d_out, int out_size) {
    const float* x   = (const float*)d_in[0];
    const int*   sel = (const int*)d_in[1];
    const float* rw  = (const float*)d_in[2];
    const float* wt[3] = {(const float*)d_in[3],  (const float*)d_in[7],  (const float*)d_in[11]};
    const float* bt[3] = {(const float*)d_in[4],  (const float*)d_in[8],  (const float*)d_in[12]};
    const float* wp[3] = {(const float*)d_in[5],  (const float*)d_in[9],  (const float*)d_in[13]};
    const float* bp[3] = {(const float*)d_in[6],  (const float*)d_in[10], (const float*)d_in[14]};
    float* out = (float*)d_out;

    float *p_x336, *p_patches, *p_feat, *p_feat2, *p_wi, *p_wbuf, *p_btp;
    cudaGetSymbolAddress((void**)&p_x336,    g_x336);
    cudaGetSymbolAddress((void**)&p_patches, g_patches);
    cudaGetSymbolAddress((void**)&p_feat,    g_feat);
    cudaGetSymbolAddress((void**)&p_feat2,   g_feat2);
    cudaGetSymbolAddress((void**)&p_wi,      g_wi);
    cudaGetSymbolAddress((void**)&p_wbuf,    g_wbuf);
    cudaGetSymbolAddress((void**)&p_btp,     g_btp);

    cudaFuncSetAttribute(tf32_gemm, cudaFuncAttributeMaxDynamicSharedMemorySize, SMEM_DYN);

    const int T = 256;
    wi_kernel<<<1, 64>>>(sel, rw);

    // Weight prep (tf32-round, K-pad to x32, N-pad E2 tower to 1280)
    auto prep = [&](const float* s, float* d, int Ks, int Kd, int Ns, int Nd, int rnd) {
        prep_kernel<<<(Kd * Nd + T - 1) / T, T>>>(s, d, Ks, Kd, Ns, Nd, rnd);
    };
    prep(wt[0], p_wbuf + OFF_WT0, 588, 608, 1024, 1024, 1);
    prep(wt[1], p_wbuf + OFF_WT1, 588, 608, 768, 768, 1);
    prep(wt[2], p_wbuf + OFF_WT2, 3072, 3072, 1152, 1280, 1);
    prep(wp[0], p_wbuf + OFF_WP0, 1024, 1024, 1024, 1024, 1);
    prep(wp[1], p_wbuf + OFF_WP1, 768, 768, 1024, 1024, 1);
    prep(wp[2], p_wbuf + OFF_WP2, 1152, 1152, 1024, 1024, 1);
    prep(bt[2], p_btp, 1, 1, 1152, 1280, 0);   // bias: pad only, no rounding

    // ---------------- Expert 0: s=448, p=14, g=32, c=1024 ------------------
    {
        int g = 32, Kp = 608, c = 1024;
        patchify_kernel<<<(BATCH * g * g * Kp + T - 1) / T, T>>>(x, 448, 14, g, 588, Kp);
        // tower: [65536 x 588] @ [588 x 1024] -> g_feat (rounded; feeds proj)
        tf32_gemm<<<dim3(c / 256, BATCH * g * g / 128), 256, SMEM_DYN>>>(
            p_patches, Kp, p_wbuf + OFF_WT0, c, Kp / 32, bt[0],
            p_feat, c, nullptr, 0, 1);
        // proj: [65536 x 1024] @ [1024 x 1024] -> out (scaled)
        tf32_gemm<<<dim3(HID / 256, BATCH * TOK / 128), 256, SMEM_DYN>>>(
            p_feat, c, p_wbuf + OFF_WP0, HID, c / 32, bp[0],
            out, HID, p_wi + 0 * BATCH, 0, 0);
    }

    // ---------------- Expert 1: s=336, p=14, g=24, c=768 -------------------
    {
        int g = 24, Kp = 608, c = 768;
        resize_img_kernel<<<(BATCH * 3 * 336 * 336 + T - 1) / T, T>>>(x);
        patchify_kernel<<<(BATCH * g * g * Kp + T - 1) / T, T>>>(p_x336, 336, 14, g, 588, Kp);
        tf32_gemm<<<dim3(c / 256, BATCH * g * g / 128), 256, SMEM_DYN>>>(
            p_patches, Kp, p_wbuf + OFF_WT1, c, Kp / 32, bt[1],
            p_feat, c, nullptr, 0, 0);
        resize_feat_kernel<<<(BATCH * TOK * c + T - 1) / T, T>>>(g, c, c);
        tf32_gemm<<<dim3(HID / 256, BATCH * TOK / 128), 256, SMEM_DYN>>>(
            p_feat2, c, p_wbuf + OFF_WP1, HID, c / 32, bp[1],
            out, HID, p_wi + 1 * BATCH, 1, 0);
    }

    // ---------------- Expert 2: s=448, p=32, g=14, c=1152 (N pad 1280) -----
    {
        int g = 14, K = 3072, c = 1152, cp = 1280;
        patchify_kernel<<<(BATCH * g * g * K + T - 1) / T, T>>>(x, 448, 32, g, K, K);
        // tower: [12544 x 3072] @ [3072 x 1280pad] -> g_feat (ldc=1280)
        tf32_gemm<<<dim3(cp / 256, BATCH * g * g / 128), 256, SMEM_DYN>>>(
            p_patches, K, p_wbuf + OFF_WT2, cp, K / 32, p_btp,
            p_feat, cp, nullptr, 0, 0);
        resize_feat_kernel<<<(BATCH * TOK * c + T - 1) / T, T>>>(g, c, cp);
        tf32_gemm<<<dim3(HID / 256, BATCH * TOK / 128), 256, SMEM_DYN>>>(
            p_feat2, c, p_wbuf + OFF_WP2, HID, c / 32, bp[2],
            out, HID, p_wi + 2 * BATCH, 1, 0);
    }
}